// round 1
// baseline (speedup 1.0000x reference)
#include <cuda_runtime.h>
#include <cstdint>

#define NBATCH 512
#define ND 128
#define NW 512
#define TSTEPS 512
#define GRID 128
#define LDA 68

// ---------------- persistent scratch (no allocations allowed) ----------------
__device__ float g_y[NBATCH * ND];
__device__ float g_k[6][NBATCH * ND];
__device__ float g_h1[NBATCH * NW];
__device__ float g_h2[NBATCH * NW];
__device__ float g_w1c[NW * ND];
__device__ float g_w2c[NW * NW];
__device__ float g_w3c[ND * NW];
__device__ float g_Ac[ND * ND];
__device__ unsigned long long g_bar = 0ULL;

// ---------------- helpers ----------------
__device__ __forceinline__ float f2tf32(float x) {
    unsigned u;
    asm("cvt.rna.tf32.f32 %0, %1;" : "=r"(u) : "f"(x));
    return __uint_as_float(u);
}

// Software grid barrier. Monotonic counter => safe across graph replays:
// each barrier's arrivals occupy a contiguous [n*G, (n+1)*G) block, so the
// target is ceil(my/G)*G regardless of how many launches preceded us.
__device__ __forceinline__ void grid_barrier() {
    __syncthreads();
    if (threadIdx.x == 0) {
        __threadfence();  // release prior writes
        unsigned long long my = atomicAdd(&g_bar, 1ULL) + 1ULL;
        unsigned long long g = (unsigned long long)gridDim.x;
        unsigned long long target = ((my + g - 1ULL) / g) * g;
        unsigned long long v;
        do {
            asm volatile("ld.acquire.gpu.u64 %0, [%1];" : "=l"(v) : "l"(&g_bar) : "memory");
        } while (v < target);
    }
    __syncthreads();
}

__device__ __forceinline__ void mma8(float* c, const unsigned* a, const unsigned* b) {
    asm volatile(
        "mma.sync.aligned.m16n8k8.row.col.f32.tf32.tf32.f32 "
        "{%0,%1,%2,%3}, {%4,%5,%6,%7}, {%8,%9}, {%0,%1,%2,%3};"
        : "+f"(c[0]), "+f"(c[1]), "+f"(c[2]), "+f"(c[3])
        : "r"(a[0]), "r"(a[1]), "r"(a[2]), "r"(a[3]), "r"(b[0]), "r"(b[1]));
}

// One 64-wide K chunk of MMAs. Warp tile 16x16 at (wm, wn) inside 64x32 CTA tile.
__device__ __forceinline__ void mma_chunk(float (*As)[LDA], float (*Bs)[LDA],
                                          float acc[2][4], int wm, int wn, int lane) {
    const int gid = lane >> 2, tig = lane & 3;
#pragma unroll
    for (int kk = 0; kk < 64; kk += 8) {
        unsigned a[4], b[2];
        a[0] = __float_as_uint(As[wm + gid][kk + tig]);
        a[1] = __float_as_uint(As[wm + gid + 8][kk + tig]);
        a[2] = __float_as_uint(As[wm + gid][kk + tig + 4]);
        a[3] = __float_as_uint(As[wm + gid + 8][kk + tig + 4]);
#pragma unroll
        for (int j = 0; j < 2; j++) {
            b[0] = __float_as_uint(Bs[wn + 8 * j + gid][kk + tig]);
            b[1] = __float_as_uint(Bs[wn + 8 * j + gid][kk + tig + 4]);
            mma8(acc[j], a, b);
        }
    }
}

// B tile: 32 rows (N) x 64 cols (K) from weight matrix stored [N][K]
__device__ __forceinline__ void load_B64(float (*Bs)[LDA], const float* __restrict__ Wm,
                                         int n0, int K, int kc, int tid) {
#pragma unroll
    for (int i = 0; i < 8; i++) {
        int idx = i * 256 + tid;
        int nl = idx >> 6, kl = idx & 63;
        Bs[nl][kl] = Wm[(n0 + nl) * K + kc + kl];
    }
}

// A tile: 64 rows (M) x 64 cols (K) from activation matrix with row stride ldk
__device__ __forceinline__ void load_A64(float (*As)[LDA], const float* __restrict__ Am,
                                         int m0, int ldk, int kc, int tid) {
#pragma unroll
    for (int i = 0; i < 16; i++) {
        int idx = i * 256 + tid;
        int ml = idx >> 6, kl = idx & 63;
        As[ml][kl] = Am[(m0 + ml) * ldk + kc + kl];
    }
}

// A tile as RK stage input Z = y + h*sum_j a_sj * k_j, computed on the fly.
__device__ __forceinline__ void load_AZ(float (*As)[LDA], int m0, int kc,
                                        int s, const float* ha, int tid) {
#pragma unroll
    for (int i = 0; i < 16; i++) {
        int idx = i * 256 + tid;
        int ml = idx >> 6, kl = idx & 63;
        int off = (m0 + ml) * ND + kc + kl;
        float z = g_y[off];
        for (int j = 0; j < s; j++) z += ha[j] * g_k[j][off];
        As[ml][kl] = f2tf32(z);
    }
}

// ---------------- persistent kernel ----------------
__global__ void __launch_bounds__(256) StabilizedNeuralODE_kernel(
    const float* __restrict__ ts, const float* __restrict__ yi,
    const float* __restrict__ w1, const float* __restrict__ b1,
    const float* __restrict__ w2, const float* __restrict__ b2,
    const float* __restrict__ w3, const float* __restrict__ b3,
    const float* __restrict__ Amat, float* __restrict__ out) {
    __shared__ float As[64][LDA];
    __shared__ float Bs[32][LDA];

    const int tid = threadIdx.x, blk = blockIdx.x;
    const int warp = tid >> 5, lane = tid & 31;
    const int gid = lane >> 2, tig = lane & 3;
    const int wm = (warp & 3) * 16, wn = (warp >> 2) * 16;
    const int gtid = blk * 256 + tid, gstride = GRID * 256;

    // ---- per-launch init: tf32-round weights, init y, write out[:,0,:] ----
    for (int i = gtid; i < NW * ND; i += gstride) g_w1c[i] = f2tf32(w1[i]);
    for (int i = gtid; i < NW * NW; i += gstride) g_w2c[i] = f2tf32(w2[i]);
    for (int i = gtid; i < ND * NW; i += gstride) g_w3c[i] = f2tf32(w3[i]);
    for (int i = gtid; i < ND * ND; i += gstride) g_Ac[i] = f2tf32(Amat[i]);
    for (int i = gtid; i < NBATCH * ND; i += gstride) {
        float v = yi[i];  // yi is [B,1,D] contiguous
        g_y[i] = v;
        int b = i / ND, d = i - b * ND;
        out[(size_t)b * (TSTEPS * ND) + d] = v;
    }
    grid_barrier();

    // RK tableau (float32, matching the reference's weak-typed scalars)
    const float AT[6][5] = {
        {0.f, 0.f, 0.f, 0.f, 0.f},
        {0.161f, 0.f, 0.f, 0.f, 0.f},
        {-0.008480655492356989f, 0.335480655492357f, 0.f, 0.f, 0.f},
        {2.8971530571054935f, -6.359448489975075f, 4.3622954328695815f, 0.f, 0.f},
        {5.325864828439257f, -11.748883564062828f, 7.4955393428898365f, -0.09249506636175525f, 0.f},
        {5.86145544294642f, -12.92096931784711f, 8.159367898576159f, -0.071584973281401f, -0.028269050394068383f}};
    const float BT[6] = {0.09646076681806523f, 0.01f, 0.4798896504144996f,
                         1.379008574103742f, -3.290069515436081f, 2.324710524099774f};

    for (int t = 0; t < TSTEPS - 1; t++) {
        const float h = ts[t + 1] - ts[t];
        for (int s = 0; s < 6; s++) {
            float ha[5];
#pragma unroll
            for (int j = 0; j < 5; j++) ha[j] = h * AT[s][j];

            // ---- G1: H1 = tanh(Z @ w1^T + b1)   M=512 N=512 K=128 ----
            {
                int tm = blk & 7, tn = blk >> 3;  // 8 x 16 tiles of 64x32
                int m0 = tm * 64, n0 = tn * 32;
                float acc[2][4] = {{0, 0, 0, 0}, {0, 0, 0, 0}};
                for (int kc = 0; kc < ND; kc += 64) {
                    load_AZ(As, m0, kc, s, ha, tid);
                    load_B64(Bs, g_w1c, n0, ND, kc, tid);
                    __syncthreads();
                    mma_chunk(As, Bs, acc, wm, wn, lane);
                    __syncthreads();
                }
#pragma unroll
                for (int j = 0; j < 2; j++) {
                    int col = n0 + wn + 8 * j + 2 * tig;
                    int r0 = m0 + wm + gid;
                    float bb0 = b1[col], bb1 = b1[col + 1];
                    g_h1[r0 * NW + col] = f2tf32(tanhf(acc[j][0] + bb0));
                    g_h1[r0 * NW + col + 1] = f2tf32(tanhf(acc[j][1] + bb1));
                    g_h1[(r0 + 8) * NW + col] = f2tf32(tanhf(acc[j][2] + bb0));
                    g_h1[(r0 + 8) * NW + col + 1] = f2tf32(tanhf(acc[j][3] + bb1));
                }
            }
            grid_barrier();

            // ---- G2: H2 = tanh(H1 @ w2^T + b2)   M=512 N=512 K=512 ----
            {
                int tm = blk & 7, tn = blk >> 3;
                int m0 = tm * 64, n0 = tn * 32;
                float acc[2][4] = {{0, 0, 0, 0}, {0, 0, 0, 0}};
                for (int kc = 0; kc < NW; kc += 64) {
                    load_A64(As, g_h1, m0, NW, kc, tid);
                    load_B64(Bs, g_w2c, n0, NW, kc, tid);
                    __syncthreads();
                    mma_chunk(As, Bs, acc, wm, wn, lane);
                    __syncthreads();
                }
#pragma unroll
                for (int j = 0; j < 2; j++) {
                    int col = n0 + wn + 8 * j + 2 * tig;
                    int r0 = m0 + wm + gid;
                    float bb0 = b2[col], bb1 = b2[col + 1];
                    g_h2[r0 * NW + col] = f2tf32(tanhf(acc[j][0] + bb0));
                    g_h2[r0 * NW + col + 1] = f2tf32(tanhf(acc[j][1] + bb1));
                    g_h2[(r0 + 8) * NW + col] = f2tf32(tanhf(acc[j][2] + bb0));
                    g_h2[(r0 + 8) * NW + col + 1] = f2tf32(tanhf(acc[j][3] + bb1));
                }
            }
            grid_barrier();

            // ---- G3: k_s = H2 @ w3^T + b3 + Z @ A^T   M=512 N=128 ----
            if (blk < 32) {
                int tm = blk & 7, tn = blk >> 3;  // 8 x 4 tiles of 64x32
                int m0 = tm * 64, n0 = tn * 32;
                float acc[2][4] = {{0, 0, 0, 0}, {0, 0, 0, 0}};
                for (int kc = 0; kc < NW; kc += 64) {
                    load_A64(As, g_h2, m0, NW, kc, tid);
                    load_B64(Bs, g_w3c, n0, NW, kc, tid);
                    __syncthreads();
                    mma_chunk(As, Bs, acc, wm, wn, lane);
                    __syncthreads();
                }
                for (int kc = 0; kc < ND; kc += 64) {
                    load_AZ(As, m0, kc, s, ha, tid);
                    load_B64(Bs, g_Ac, n0, ND, kc, tid);
                    __syncthreads();
                    mma_chunk(As, Bs, acc, wm, wn, lane);
                    __syncthreads();
                }
                float* ks = g_k[s];
#pragma unroll
                for (int j = 0; j < 2; j++) {
                    int col = n0 + wn + 8 * j + 2 * tig;
#pragma unroll
                    for (int e = 0; e < 4; e++) {
                        int r = m0 + wm + gid + ((e >= 2) ? 8 : 0);
                        int c = col + (e & 1);
                        float kv = acc[j][e] + b3[c];
                        int off = r * ND + c;
                        ks[off] = kv;
                        if (s == 5) {
                            float yv = g_y[off] +
                                       h * (BT[0] * g_k[0][off] + BT[1] * g_k[1][off] +
                                            BT[2] * g_k[2][off] + BT[3] * g_k[3][off] +
                                            BT[4] * g_k[4][off] + BT[5] * kv);
                            g_y[off] = yv;
                            out[(size_t)r * (TSTEPS * ND) + (size_t)(t + 1) * ND + c] = yv;
                        }
                    }
                }
            }
            grid_barrier();
        }
    }
}

// ---------------- launch ----------------
extern "C" void kernel_launch(void* const* d_in, const int* in_sizes, int n_in,
                              void* d_out, int out_size) {
    const float* ts = (const float*)d_in[0];
    const float* yi = (const float*)d_in[1];
    const float* w1 = (const float*)d_in[2];
    const float* b1 = (const float*)d_in[3];
    const float* w2 = (const float*)d_in[4];
    const float* b2 = (const float*)d_in[5];
    const float* w3 = (const float*)d_in[6];
    const float* b3 = (const float*)d_in[7];
    const float* A = (const float*)d_in[8];
    float* out = (float*)d_out;
    StabilizedNeuralODE_kernel<<<GRID, 256>>>(ts, yi, w1, b1, w2, b2, w3, b3, A, out);
}

// round 2
// speedup vs baseline: 1.0121x; 1.0121x over previous
#include <cuda_runtime.h>
#include <cstdint>

#define NBATCH 512
#define ND 128
#define NW 512
#define TSTEPS 512
#define GRID 128
#define LDA 68

// ---------------- persistent scratch (no allocations allowed) ----------------
__device__ float g_y[NBATCH * ND];
__device__ float g_k[6][NBATCH * ND];
__device__ float g_h1[NBATCH * NW];
__device__ float g_h2[NBATCH * NW];
__device__ float g_w1c[NW * ND];
__device__ float g_w2c[NW * NW];
__device__ float g_w3c[ND * NW];
__device__ float g_Ac[ND * ND];
__device__ unsigned long long g_bar = 0ULL;

// ---------------- helpers ----------------
__device__ __forceinline__ float f2tf32(float x) {
    unsigned u;
    asm("cvt.rna.tf32.f32 %0, %1;" : "=r"(u) : "f"(x));
    return __uint_as_float(u);
}

// Software grid barrier. Monotonic counter => safe across graph replays:
// each barrier's arrivals occupy a contiguous [n*G, (n+1)*G) block, so the
// target is ceil(my/G)*G regardless of how many launches preceded us.
__device__ __forceinline__ void grid_barrier() {
    __syncthreads();
    if (threadIdx.x == 0) {
        __threadfence();  // release prior writes
        unsigned long long my = atomicAdd(&g_bar, 1ULL) + 1ULL;
        unsigned long long g = (unsigned long long)gridDim.x;
        unsigned long long target = ((my + g - 1ULL) / g) * g;
        unsigned long long v;
        do {
            asm volatile("ld.acquire.gpu.u64 %0, [%1];" : "=l"(v) : "l"(&g_bar) : "memory");
        } while (v < target);
    }
    __syncthreads();
}

__device__ __forceinline__ void mma8(float* c, const unsigned* a, const unsigned* b) {
    asm volatile(
        "mma.sync.aligned.m16n8k8.row.col.f32.tf32.tf32.f32 "
        "{%0,%1,%2,%3}, {%4,%5,%6,%7}, {%8,%9}, {%0,%1,%2,%3};"
        : "+f"(c[0]), "+f"(c[1]), "+f"(c[2]), "+f"(c[3])
        : "r"(a[0]), "r"(a[1]), "r"(a[2]), "r"(a[3]), "r"(b[0]), "r"(b[1]));
}

// One 64-wide K chunk of MMAs. Warp tile 16x16 at (wm, wn) inside 64x32 CTA tile.
__device__ __forceinline__ void mma_chunk(float (*As)[LDA], float (*Bs)[LDA],
                                          float acc[2][4], int wm, int wn, int lane) {
    const int gid = lane >> 2, tig = lane & 3;
#pragma unroll
    for (int kk = 0; kk < 64; kk += 8) {
        unsigned a[4], b[2];
        a[0] = __float_as_uint(As[wm + gid][kk + tig]);
        a[1] = __float_as_uint(As[wm + gid + 8][kk + tig]);
        a[2] = __float_as_uint(As[wm + gid][kk + tig + 4]);
        a[3] = __float_as_uint(As[wm + gid + 8][kk + tig + 4]);
#pragma unroll
        for (int j = 0; j < 2; j++) {
            b[0] = __float_as_uint(Bs[wn + 8 * j + gid][kk + tig]);
            b[1] = __float_as_uint(Bs[wn + 8 * j + gid][kk + tig + 4]);
            mma8(acc[j], a, b);
        }
    }
}

// B tile: 32 rows (N) x 64 cols (K) from weight matrix stored [N][K]
__device__ __forceinline__ void load_B64(float (*Bs)[LDA], const float* __restrict__ Wm,
                                         int n0, int K, int kc, int tid) {
#pragma unroll
    for (int i = 0; i < 8; i++) {
        int idx = i * 256 + tid;
        int nl = idx >> 6, kl = idx & 63;
        Bs[nl][kl] = Wm[(n0 + nl) * K + kc + kl];
    }
}

// A tile: 64 rows (M) x 64 cols (K) from activation matrix with row stride ldk
__device__ __forceinline__ void load_A64(float (*As)[LDA], const float* __restrict__ Am,
                                         int m0, int ldk, int kc, int tid) {
#pragma unroll
    for (int i = 0; i < 16; i++) {
        int idx = i * 256 + tid;
        int ml = idx >> 6, kl = idx & 63;
        As[ml][kl] = Am[(m0 + ml) * ldk + kc + kl];
    }
}

// A tile as RK stage input Z = y + h*sum_j a_sj * k_j, computed on the fly.
__device__ __forceinline__ void load_AZ(float (*As)[LDA], int m0, int kc,
                                        int s, const float* ha, int tid) {
#pragma unroll
    for (int i = 0; i < 16; i++) {
        int idx = i * 256 + tid;
        int ml = idx >> 6, kl = idx & 63;
        int off = (m0 + ml) * ND + kc + kl;
        float z = g_y[off];
        for (int j = 0; j < s; j++) z += ha[j] * g_k[j][off];
        As[ml][kl] = f2tf32(z);
    }
}

// ---------------- persistent kernel ----------------
__global__ void __launch_bounds__(256) StabilizedNeuralODE_kernel(
    const float* __restrict__ ts, const float* __restrict__ yi,
    const float* __restrict__ w1, const float* __restrict__ b1,
    const float* __restrict__ w2, const float* __restrict__ b2,
    const float* __restrict__ w3, const float* __restrict__ b3,
    const float* __restrict__ Amat, float* __restrict__ out) {
    __shared__ float As[64][LDA];
    __shared__ float Bs[32][LDA];

    const int tid = threadIdx.x, blk = blockIdx.x;
    const int warp = tid >> 5, lane = tid & 31;
    const int gid = lane >> 2, tig = lane & 3;
    const int wm = (warp & 3) * 16, wn = (warp >> 2) * 16;
    const int gtid = blk * 256 + tid, gstride = GRID * 256;

    // ---- per-launch init: tf32-round weights, init y, write out[:,0,:] ----
    for (int i = gtid; i < NW * ND; i += gstride) g_w1c[i] = f2tf32(w1[i]);
    for (int i = gtid; i < NW * NW; i += gstride) g_w2c[i] = f2tf32(w2[i]);
    for (int i = gtid; i < ND * NW; i += gstride) g_w3c[i] = f2tf32(w3[i]);
    for (int i = gtid; i < ND * ND; i += gstride) g_Ac[i] = f2tf32(Amat[i]);
    for (int i = gtid; i < NBATCH * ND; i += gstride) {
        float v = yi[i];  // yi is [B,1,D] contiguous
        g_y[i] = v;
        int b = i / ND, d = i - b * ND;
        out[(size_t)b * (TSTEPS * ND) + d] = v;
    }
    grid_barrier();

    // RK tableau (float32, matching the reference's weak-typed scalars)
    const float AT[6][5] = {
        {0.f, 0.f, 0.f, 0.f, 0.f},
        {0.161f, 0.f, 0.f, 0.f, 0.f},
        {-0.008480655492356989f, 0.335480655492357f, 0.f, 0.f, 0.f},
        {2.8971530571054935f, -6.359448489975075f, 4.3622954328695815f, 0.f, 0.f},
        {5.325864828439257f, -11.748883564062828f, 7.4955393428898365f, -0.09249506636175525f, 0.f},
        {5.86145544294642f, -12.92096931784711f, 8.159367898576159f, -0.071584973281401f, -0.028269050394068383f}};
    const float BT[6] = {0.09646076681806523f, 0.01f, 0.4798896504144996f,
                         1.379008574103742f, -3.290069515436081f, 2.324710524099774f};

    for (int t = 0; t < TSTEPS - 1; t++) {
        const float h = ts[t + 1] - ts[t];
        for (int s = 0; s < 6; s++) {
            float ha[5];
#pragma unroll
            for (int j = 0; j < 5; j++) ha[j] = h * AT[s][j];

            // ---- G1: H1 = tanh(Z @ w1^T + b1)   M=512 N=512 K=128 ----
            {
                int tm = blk & 7, tn = blk >> 3;  // 8 x 16 tiles of 64x32
                int m0 = tm * 64, n0 = tn * 32;
                float acc[2][4] = {{0, 0, 0, 0}, {0, 0, 0, 0}};
                for (int kc = 0; kc < ND; kc += 64) {
                    load_AZ(As, m0, kc, s, ha, tid);
                    load_B64(Bs, g_w1c, n0, ND, kc, tid);
                    __syncthreads();
                    mma_chunk(As, Bs, acc, wm, wn, lane);
                    __syncthreads();
                }
#pragma unroll
                for (int j = 0; j < 2; j++) {
                    int col = n0 + wn + 8 * j + 2 * tig;
                    int r0 = m0 + wm + gid;
                    float bb0 = b1[col], bb1 = b1[col + 1];
                    g_h1[r0 * NW + col] = f2tf32(tanhf(acc[j][0] + bb0));
                    g_h1[r0 * NW + col + 1] = f2tf32(tanhf(acc[j][1] + bb1));
                    g_h1[(r0 + 8) * NW + col] = f2tf32(tanhf(acc[j][2] + bb0));
                    g_h1[(r0 + 8) * NW + col + 1] = f2tf32(tanhf(acc[j][3] + bb1));
                }
            }
            grid_barrier();

            // ---- G2: H2 = tanh(H1 @ w2^T + b2)   M=512 N=512 K=512 ----
            {
                int tm = blk & 7, tn = blk >> 3;
                int m0 = tm * 64, n0 = tn * 32;
                float acc[2][4] = {{0, 0, 0, 0}, {0, 0, 0, 0}};
                for (int kc = 0; kc < NW; kc += 64) {
                    load_A64(As, g_h1, m0, NW, kc, tid);
                    load_B64(Bs, g_w2c, n0, NW, kc, tid);
                    __syncthreads();
                    mma_chunk(As, Bs, acc, wm, wn, lane);
                    __syncthreads();
                }
#pragma unroll
                for (int j = 0; j < 2; j++) {
                    int col = n0 + wn + 8 * j + 2 * tig;
                    int r0 = m0 + wm + gid;
                    float bb0 = b2[col], bb1 = b2[col + 1];
                    g_h2[r0 * NW + col] = f2tf32(tanhf(acc[j][0] + bb0));
                    g_h2[r0 * NW + col + 1] = f2tf32(tanhf(acc[j][1] + bb1));
                    g_h2[(r0 + 8) * NW + col] = f2tf32(tanhf(acc[j][2] + bb0));
                    g_h2[(r0 + 8) * NW + col + 1] = f2tf32(tanhf(acc[j][3] + bb1));
                }
            }
            grid_barrier();

            // ---- G3: k_s = H2 @ w3^T + b3 + Z @ A^T   M=512 N=128 ----
            if (blk < 32) {
                int tm = blk & 7, tn = blk >> 3;  // 8 x 4 tiles of 64x32
                int m0 = tm * 64, n0 = tn * 32;
                float acc[2][4] = {{0, 0, 0, 0}, {0, 0, 0, 0}};
                for (int kc = 0; kc < NW; kc += 64) {
                    load_A64(As, g_h2, m0, NW, kc, tid);
                    load_B64(Bs, g_w3c, n0, NW, kc, tid);
                    __syncthreads();
                    mma_chunk(As, Bs, acc, wm, wn, lane);
                    __syncthreads();
                }
                for (int kc = 0; kc < ND; kc += 64) {
                    load_AZ(As, m0, kc, s, ha, tid);
                    load_B64(Bs, g_Ac, n0, ND, kc, tid);
                    __syncthreads();
                    mma_chunk(As, Bs, acc, wm, wn, lane);
                    __syncthreads();
                }
                float* ks = g_k[s];
#pragma unroll
                for (int j = 0; j < 2; j++) {
                    int col = n0 + wn + 8 * j + 2 * tig;
#pragma unroll
                    for (int e = 0; e < 4; e++) {
                        int r = m0 + wm + gid + ((e >= 2) ? 8 : 0);
                        int c = col + (e & 1);
                        float kv = acc[j][e] + b3[c];
                        int off = r * ND + c;
                        ks[off] = kv;
                        if (s == 5) {
                            float yv = g_y[off] +
                                       h * (BT[0] * g_k[0][off] + BT[1] * g_k[1][off] +
                                            BT[2] * g_k[2][off] + BT[3] * g_k[3][off] +
                                            BT[4] * g_k[4][off] + BT[5] * kv);
                            g_y[off] = yv;
                            out[(size_t)r * (TSTEPS * ND) + (size_t)(t + 1) * ND + c] = yv;
                        }
                    }
                }
            }
            grid_barrier();
        }
    }
}

// ---------------- launch ----------------
extern "C" void kernel_launch(void* const* d_in, const int* in_sizes, int n_in,
                              void* d_out, int out_size) {
    const float* ts = (const float*)d_in[0];
    const float* yi = (const float*)d_in[1];
    const float* w1 = (const float*)d_in[2];
    const float* b1 = (const float*)d_in[3];
    const float* w2 = (const float*)d_in[4];
    const float* b2 = (const float*)d_in[5];
    const float* w3 = (const float*)d_in[6];
    const float* b3 = (const float*)d_in[7];
    const float* A = (const float*)d_in[8];
    float* out = (float*)d_out;
    StabilizedNeuralODE_kernel<<<GRID, 256>>>(ts, yi, w1, b1, w2, b2, w3, b3, A, out);
}

// round 3
// speedup vs baseline: 1.9412x; 1.9179x over previous
#include <cuda_runtime.h>
#include <cstdint>

#define NB 512
#define DD 128
#define WW 512
#define TT 512

// SMEM layout (float offsets)
#define O_W2 0
#define O_W1 (O_W2 + 64*516)
#define O_AM (O_W1 + 64*132)
#define O_Z  (O_AM + 16*132)
#define O_AS (O_Z  + 32*132)
#define O_BS (O_AS + 2*32*68)
#define SMF  (O_BS + 2*16*68)   // 54336 floats = 217,344 B

__device__ __align__(16) float g_h1[NB*WW];
__device__ __align__(16) float g_h2[NB*WW];
__device__ __align__(16) float g_k[6][NB*DD];
__device__ __align__(16) float g_y[NB*DD];

__constant__ float c_AT[6][5] = {
    {0.f,0.f,0.f,0.f,0.f},
    {0.161f,0.f,0.f,0.f,0.f},
    {-0.008480655492356989f,0.335480655492357f,0.f,0.f,0.f},
    {2.8971530571054935f,-6.359448489975075f,4.3622954328695815f,0.f,0.f},
    {5.325864828439257f,-11.748883564062828f,7.4955393428898365f,-0.09249506636175525f,0.f},
    {5.86145544294642f,-12.92096931784711f,8.159367898576159f,-0.071584973281401f,-0.028269050394068383f}};
__constant__ float c_BT[6] = {0.09646076681806523f,0.01f,0.4798896504144996f,
                              1.379008574103742f,-3.290069515436081f,2.324710524099774f};

__device__ __forceinline__ float f2tf32(float x){
    unsigned u; asm("cvt.rna.tf32.f32 %0,%1;":"=r"(u):"f"(x)); return __uint_as_float(u);}
__device__ __forceinline__ void mma8(float* c,const unsigned* a,const unsigned* b){
    asm volatile("mma.sync.aligned.m16n8k8.row.col.f32.tf32.tf32.f32 "
        "{%0,%1,%2,%3},{%4,%5,%6,%7},{%8,%9},{%0,%1,%2,%3};"
        :"+f"(c[0]),"+f"(c[1]),"+f"(c[2]),"+f"(c[3])
        :"r"(a[0]),"r"(a[1]),"r"(a[2]),"r"(a[3]),"r"(b[0]),"r"(b[1]));}
__device__ __forceinline__ void cpa(uint32_t d,const float* s){
    asm volatile("cp.async.cg.shared.global [%0],[%1],16;"::"r"(d),"l"(s):"memory");}
__device__ __forceinline__ void cpc(){asm volatile("cp.async.commit_group;":::"memory");}
__device__ __forceinline__ void cpw1(){asm volatile("cp.async.wait_group 1;":::"memory");}
__device__ __forceinline__ void cpw0(){asm volatile("cp.async.wait_group 0;":::"memory");}
__device__ __forceinline__ void cbar(){
    __threadfence();
    asm volatile("barrier.cluster.arrive.aligned;":::"memory");
    asm volatile("barrier.cluster.wait.aligned;":::"memory");}

// A chunk: 32 rows x 64 cols -> SMEM stride 68
__device__ __forceinline__ void ldA(uint32_t dst,const float* src,int ld,int tid){
#pragma unroll
    for(int i=0;i<2;i++){int g=tid+i*256;int r=g>>4,c=(g&15)<<2;
        cpa(dst+(uint32_t)(r*68+c)*4u, src+(size_t)r*ld+c);}}
// B chunk: 16 rows x 64 cols -> SMEM stride 68
__device__ __forceinline__ void ldB(uint32_t dst,const float* src,int ld,int tid){
    int r=tid>>4,c=(tid&15)<<2;
    cpa(dst+(uint32_t)(r*68+c)*4u, src+(size_t)r*ld+c);}

// 64-wide K chunk, warp tile m16 x n16
__device__ __forceinline__ void mma_n16(const float* A,int lda,const float* B,int ldb,
        float acc[2][4],int wm,int wn,int gid,int tig){
#pragma unroll
    for(int kk=0;kk<64;kk+=8){
        unsigned a[4],b[2];
        a[0]=__float_as_uint(A[(wm+gid)*lda+kk+tig]);
        a[1]=__float_as_uint(A[(wm+gid+8)*lda+kk+tig]);
        a[2]=__float_as_uint(A[(wm+gid)*lda+kk+tig+4]);
        a[3]=__float_as_uint(A[(wm+gid+8)*lda+kk+tig+4]);
#pragma unroll
        for(int j=0;j<2;j++){
            b[0]=__float_as_uint(B[(wn+8*j+gid)*ldb+kk+tig]);
            b[1]=__float_as_uint(B[(wn+8*j+gid)*ldb+kk+tig+4]);
            mma8(acc[j],a,b);}}}

// 64-wide K chunk, warp tile m16 x n8
__device__ __forceinline__ void mma_n8(const float* A,int lda,const float* B,int ldb,
        float acc[4],int wm,int wn8,int gid,int tig){
#pragma unroll
    for(int kk=0;kk<64;kk+=8){
        unsigned a[4],b[2];
        a[0]=__float_as_uint(A[(wm+gid)*lda+kk+tig]);
        a[1]=__float_as_uint(A[(wm+gid+8)*lda+kk+tig]);
        a[2]=__float_as_uint(A[(wm+gid)*lda+kk+tig+4]);
        a[3]=__float_as_uint(A[(wm+gid+8)*lda+kk+tig+4]);
        b[0]=__float_as_uint(B[(wn8+gid)*ldb+kk+tig]);
        b[1]=__float_as_uint(B[(wn8+gid)*ldb+kk+tig+4]);
        mma8(acc,a,b);}}

__device__ __forceinline__ void epi_tanh(float acc[2][4],float* gH,const float* bias,
        int m0,int wm,int n0h,int wn,int gid,int tig){
#pragma unroll
    for(int j=0;j<2;j++){
        int cg=n0h+wn+8*j+2*tig;
        float b0=bias[cg],b1v=bias[cg+1];
        int r0=m0+wm+gid;
        float2 v0=make_float2(f2tf32(tanhf(acc[j][0]+b0)),f2tf32(tanhf(acc[j][1]+b1v)));
        float2 v1=make_float2(f2tf32(tanhf(acc[j][2]+b0)),f2tf32(tanhf(acc[j][3]+b1v)));
        __stcg((float2*)(gH+(size_t)r0*WW+cg),v0);
        __stcg((float2*)(gH+(size_t)(r0+8)*WW+cg),v1);}}

__global__ void __launch_bounds__(256,1) ode_kernel(
        const float* __restrict__ ts,const float* __restrict__ yi,
        const float* __restrict__ w1,const float* __restrict__ b1,
        const float* __restrict__ w2,const float* __restrict__ b2,
        const float* __restrict__ w3,const float* __restrict__ b3,
        const float* __restrict__ Am,float* __restrict__ out){
    extern __shared__ float sm[];
    const int tid=threadIdx.x, wid=tid>>5, lane=tid&31;
    const int gid=lane>>2, tig=lane&3;
    const int wm=(wid&1)*16, wn=(wid>>1)*16;         // G1/G2: M32 x N64
    const int wm3=(wid&1)*16, wn8=((wid>>1)&1)*8;    // G3: M32 x N16, warps 0-3
    const int rank=blockIdx.x&7, clus=blockIdx.x>>3;
    const int m0=clus*32, n0h=rank*64, n0k=rank*16;
    const uint32_t asb=(uint32_t)__cvta_generic_to_shared(sm+O_AS);
    const uint32_t bsb=(uint32_t)__cvta_generic_to_shared(sm+O_BS);

    // ---- init: SMEM-resident tf32 weights (slices), y, out[:,0,:] ----
    for(int i=tid;i<64*512;i+=256){int n=i>>9,k=i&511;
        sm[O_W2+n*516+k]=f2tf32(w2[(size_t)(n0h+n)*WW+k]);}
    for(int i=tid;i<64*128;i+=256){int n=i>>7,k=i&127;
        sm[O_W1+n*132+k]=f2tf32(w1[(size_t)(n0h+n)*DD+k]);}
    for(int i=tid;i<16*128;i+=256){int n=i>>7,k=i&127;
        sm[O_AM+n*132+k]=f2tf32(Am[(size_t)(n0k+n)*DD+k]);}
    for(int i=rank*256+tid;i<32*128;i+=2048){
        int r=i>>7,c=i&127; float v=yi[(size_t)(m0+r)*DD+c];
        __stcg(g_y+(size_t)(m0+r)*DD+c,v);
        out[(size_t)(m0+r)*TT*DD+c]=v;}
    cbar();

    for(int t=0;t<TT-1;t++){
        const float h=ts[t+1]-ts[t];
        for(int s=0;s<6;s++){
            float ha[5];
#pragma unroll
            for(int j=0;j<5;j++) ha[j]=h*c_AT[s][j];

            // ---- Z = y + h*sum a_sj k_j  (32x128 in SMEM, tf32) ----
            for(int i=tid;i<1024;i+=256){
                int r=i>>5,c=(i&31)<<2; size_t off=(size_t)(m0+r)*DD+c;
                float4 z=__ldcg((const float4*)(g_y+off));
                for(int j=0;j<s;j++){
                    float a=ha[j]; float4 kk=__ldcg((const float4*)(g_k[j]+off));
                    z.x+=a*kk.x; z.y+=a*kk.y; z.z+=a*kk.z; z.w+=a*kk.w;}
                float4 zt=make_float4(f2tf32(z.x),f2tf32(z.y),f2tf32(z.z),f2tf32(z.w));
                *(float4*)(sm+O_Z+r*132+c)=zt;}
            __syncthreads();

            // ---- G1: H1 = tanh(Z @ w1s^T + b1), all SMEM-resident ----
            {
                float acc[2][4]={{0,0,0,0},{0,0,0,0}};
                mma_n16(sm+O_Z,132,sm+O_W1,132,acc,wm,wn,gid,tig);
                mma_n16(sm+O_Z+64,132,sm+O_W1+64,132,acc,wm,wn,gid,tig);
                epi_tanh(acc,g_h1,b1,m0,wm,n0h,wn,gid,tig);
            }
            cbar();

            // ---- G2: H2 = tanh(H1 @ w2s^T + b2), A streamed, B resident ----
            {
                float acc[2][4]={{0,0,0,0},{0,0,0,0}};
                ldA(asb,g_h1+(size_t)m0*WW,WW,tid); cpc();
                for(int ck=0;ck<8;ck++){
                    if(ck<7){ldA(asb+((ck+1)&1)*(32*68*4),g_h1+(size_t)m0*WW+(ck+1)*64,WW,tid);
                             cpc(); cpw1();}
                    else cpw0();
                    __syncthreads();
                    mma_n16(sm+O_AS+(ck&1)*(32*68),68,sm+O_W2+ck*64,516,acc,wm,wn,gid,tig);
                    __syncthreads();}
                epi_tanh(acc,g_h2,b2,m0,wm,n0h,wn,gid,tig);
            }
            cbar();

            // ---- G3: k_s = H2 @ w3^T + b3 + Z @ A^T  (M32 x N16) ----
            {
                float acc[4]={0,0,0,0};
                ldA(asb,g_h2+(size_t)m0*WW,WW,tid);
                ldB(bsb,w3+(size_t)n0k*WW,WW,tid); cpc();
                for(int ck=0;ck<8;ck++){
                    if(ck<7){ldA(asb+((ck+1)&1)*(32*68*4),g_h2+(size_t)m0*WW+(ck+1)*64,WW,tid);
                             ldB(bsb+((ck+1)&1)*(16*68*4),w3+(size_t)n0k*WW+(ck+1)*64,WW,tid);
                             cpc(); cpw1();}
                    else cpw0();
                    __syncthreads();
                    if(wid<4) mma_n8(sm+O_AS+(ck&1)*(32*68),68,sm+O_BS+(ck&1)*(16*68),68,
                                     acc,wm3,wn8,gid,tig);
                    __syncthreads();}
                if(wid<4){
                    mma_n8(sm+O_Z,132,sm+O_AM,132,acc,wm3,wn8,gid,tig);
                    mma_n8(sm+O_Z+64,132,sm+O_AM+64,132,acc,wm3,wn8,gid,tig);
                    float* ks=g_k[s];
                    int cg=n0k+wn8+2*tig;
                    float b30=b3[cg],b31=b3[cg+1];
#pragma unroll
                    for(int e=0;e<4;e++){
                        int r=m0+wm3+gid+((e>=2)?8:0);
                        int c=cg+(e&1);
                        float kv=acc[e]+((e&1)?b31:b30);
                        size_t off=(size_t)r*DD+c;
                        __stcg(ks+off,kv);
                        if(s==5){
                            float yv=__ldcg(g_y+off)+h*(c_BT[0]*__ldcg(g_k[0]+off)
                                +c_BT[1]*__ldcg(g_k[1]+off)+c_BT[2]*__ldcg(g_k[2]+off)
                                +c_BT[3]*__ldcg(g_k[3]+off)+c_BT[4]*__ldcg(g_k[4]+off)
                                +c_BT[5]*kv);
                            __stcg(g_y+off,yv);
                            out[(size_t)r*TT*DD+(size_t)(t+1)*DD+c]=yv;}}}
            }
            cbar();
        }
    }
}

extern "C" void kernel_launch(void* const* d_in,const int* in_sizes,int n_in,
                              void* d_out,int out_size){
    (void)in_sizes;(void)n_in;(void)out_size;
    cudaFuncSetAttribute(ode_kernel,cudaFuncAttributeMaxDynamicSharedMemorySize,SMF*4);
    cudaLaunchConfig_t cfg={};
    cfg.gridDim=dim3(128,1,1);
    cfg.blockDim=dim3(256,1,1);
    cfg.dynamicSmemBytes=SMF*4;
    cudaLaunchAttribute at[1];
    at[0].id=cudaLaunchAttributeClusterDimension;
    at[0].val.clusterDim.x=8; at[0].val.clusterDim.y=1; at[0].val.clusterDim.z=1;
    cfg.attrs=at; cfg.numAttrs=1;
    cudaLaunchKernelEx(&cfg,ode_kernel,
        (const float*)d_in[0],(const float*)d_in[1],(const float*)d_in[2],
        (const float*)d_in[3],(const float*)d_in[4],(const float*)d_in[5],
        (const float*)d_in[6],(const float*)d_in[7],(const float*)d_in[8],
        (float*)d_out);
}

// round 4
// speedup vs baseline: 2.2899x; 1.1796x over previous
#include <cuda_runtime.h>
#include <cstdint>

#define NB 512
#define DD 128
#define WW 512
#define TT 512
#define NTHR 512

// SMEM float offsets
#define O_W2 0                     // 64 x 516
#define O_W1 (O_W2 + 64*516)       // 64 x 132
#define O_W3 (O_W1 + 64*132)       // 16 x 516
#define O_AM (O_W3 + 16*516)       // 16 x 132
#define O_SA (O_AM + 16*132)       // 2 x (32 x 68) staging / Z / partials
#define O_B  (O_SA + 2*32*68)      // biases: 64 + 64 + 16
#define SMF  (O_B + 160)           // 56352 floats = 225,408 B

__device__ __align__(16) float g_h1[NB*WW];
__device__ __align__(16) float g_h2[NB*WW];
__device__ __align__(16) float g_k[6][NB*DD];
__device__ __align__(16) float g_y[NB*DD];

__constant__ float c_AT[6][5] = {
    {0.f,0.f,0.f,0.f,0.f},
    {0.161f,0.f,0.f,0.f,0.f},
    {-0.008480655492356989f,0.335480655492357f,0.f,0.f,0.f},
    {2.8971530571054935f,-6.359448489975075f,4.3622954328695815f,0.f,0.f},
    {5.325864828439257f,-11.748883564062828f,7.4955393428898365f,-0.09249506636175525f,0.f},
    {5.86145544294642f,-12.92096931784711f,8.159367898576159f,-0.071584973281401f,-0.028269050394068383f}};
__constant__ float c_BT[6] = {0.09646076681806523f,0.01f,0.4798896504144996f,
                              1.379008574103742f,-3.290069515436081f,2.324710524099774f};

__device__ __forceinline__ float f2tf32(float x){
    unsigned u; asm("cvt.rna.tf32.f32 %0,%1;":"=r"(u):"f"(x)); return __uint_as_float(u);}
__device__ __forceinline__ float ftanh(float x){
    float e = exp2f(2.885390081777927f * x);       // e^(2x)
    return 1.0f - __fdividef(2.0f, e + 1.0f);}
__device__ __forceinline__ void mma8(float* c,const unsigned* a,const unsigned* b){
    asm volatile("mma.sync.aligned.m16n8k8.row.col.f32.tf32.tf32.f32 "
        "{%0,%1,%2,%3},{%4,%5,%6,%7},{%8,%9},{%0,%1,%2,%3};"
        :"+f"(c[0]),"+f"(c[1]),"+f"(c[2]),"+f"(c[3])
        :"r"(a[0]),"r"(a[1]),"r"(a[2]),"r"(a[3]),"r"(b[0]),"r"(b[1]));}
__device__ __forceinline__ unsigned sma(const float* p){
    return (unsigned)__cvta_generic_to_shared(p);}
__device__ __forceinline__ void ldsm4(unsigned r[4], const float* p){
    asm volatile("ldmatrix.sync.aligned.m8n8.x4.shared.b16 {%0,%1,%2,%3},[%4];"
        :"=r"(r[0]),"=r"(r[1]),"=r"(r[2]),"=r"(r[3]):"r"(sma(p)));}
__device__ __forceinline__ void ldsm2(unsigned r[2], const float* p){
    asm volatile("ldmatrix.sync.aligned.m8n8.x2.shared.b16 {%0,%1},[%2];"
        :"=r"(r[0]),"=r"(r[1]):"r"(sma(p)));}
__device__ __forceinline__ void cpa(uint32_t d,const float* s){
    asm volatile("cp.async.cg.shared.global [%0],[%1],16;"::"r"(d),"l"(s):"memory");}
__device__ __forceinline__ void cpc(){asm volatile("cp.async.commit_group;":::"memory");}
__device__ __forceinline__ void cpw1(){asm volatile("cp.async.wait_group 1;":::"memory");}
__device__ __forceinline__ void cpw0(){asm volatile("cp.async.wait_group 0;":::"memory");}
__device__ __forceinline__ void cbar(){
    asm volatile("barrier.cluster.arrive.aligned;":::"memory");
    asm volatile("barrier.cluster.wait.aligned;":::"memory");}

// stage one 32x64 chunk of A (row stride WW in gmem) into SMEM stride 68
__device__ __forceinline__ void ldA512(uint32_t dstb,const float* src,int tid){
    int r=tid>>4, g=(tid&15)<<2;
    cpa(dstb + (uint32_t)(r*68+g)*4u, src + (size_t)r*WW + g);}

// build Z chunk (32 rows x 64 cols from col c0) into dst (stride 68), tf32-rounded
__device__ __forceinline__ void buildZ(float* dst,int m0,int c0,int s,const float* ha,int tid){
    int r=tid>>4, g=(tid&15)<<2;
    size_t off=(size_t)(m0+r)*DD + c0 + g;
    float4 z=__ldcg((const float4*)(g_y+off));
    for(int j=0;j<s;j++){
        float a=ha[j]; float4 kk=__ldcg((const float4*)(g_k[j]+off));
        z.x+=a*kk.x; z.y+=a*kk.y; z.z+=a*kk.z; z.w+=a*kk.w;}
    *(float4*)(dst+r*68+g)=make_float4(f2tf32(z.x),f2tf32(z.y),f2tf32(z.z),f2tf32(z.w));}

// m16n16, 4 K8-steps selected by ks (0/1) within a 64-wide chunk
__device__ __forceinline__ void mma_n16(const float* At,int lda,const float* Bt,int ldb,
        float acc[2][4],int wm,int wn,int ks,int lane){
    const float* ap = At + (wm + (lane&15))*lda + ((lane>>4)<<2) + ks*32;
    const float* bp = Bt + (wn + (lane&7) + ((lane>>4)<<3))*ldb + (((lane>>3)&1)<<2) + ks*32;
#pragma unroll
    for(int kk=0;kk<32;kk+=8){
        unsigned a[4],b[4];
        ldsm4(a, ap+kk); ldsm4(b, bp+kk);
        mma8(acc[0],a,b); mma8(acc[1],a,b+2);}}

// m16n8, 2 K8-steps selected by ks (0..3)
__device__ __forceinline__ void mma_n8(const float* At,int lda,const float* Bt,int ldb,
        float acc[4],int wm,int wn8,int ks,int lane){
    const float* ap = At + (wm + (lane&15))*lda + ((lane>>4)<<2) + ks*16;
    const float* bp = Bt + (wn8 + (lane&7))*ldb + (((lane>>3)&1)<<2) + ks*16;
#pragma unroll
    for(int kk=0;kk<16;kk+=8){
        unsigned a[4],b[2];
        ldsm4(a, ap+kk); ldsm2(b, bp+kk);
        mma8(acc,a,b);}}

__global__ void __launch_bounds__(NTHR,1) ode_kernel(
        const float* __restrict__ ts,const float* __restrict__ yi,
        const float* __restrict__ w1,const float* __restrict__ b1,
        const float* __restrict__ w2,const float* __restrict__ b2,
        const float* __restrict__ w3,const float* __restrict__ b3,
        const float* __restrict__ Am,float* __restrict__ out){
    extern __shared__ float sm[];
    const int tid=threadIdx.x, wid=tid>>5, lane=tid&31;
    const int gid=lane>>2, tig=lane&3;
    // G1/G2: 2M x 4N x 2K-split of m16n16
    const int wm=(wid&1)*16, wn=((wid>>1)&3)*16, ks2=wid>>3;
    // G3: 2M x 2N(n8) x 4K-split
    const int wn8=((wid>>1)&1)*8, ks4=wid>>2;
    const int rank=blockIdx.x&7, clus=blockIdx.x>>3;
    const int m0=clus*32, n0h=rank*64, n0k=rank*16;
    float* buf0=sm+O_SA; float* buf1=sm+O_SA+32*68;
    const uint32_t b0b=(uint32_t)__cvta_generic_to_shared(buf0);
    const uint32_t b1b=(uint32_t)__cvta_generic_to_shared(buf1);

    // ---- init: resident tf32 weights, biases, y, out[:,0,:] ----
    for(int i=tid;i<64*512;i+=NTHR){int n=i>>9,k=i&511;
        sm[O_W2+n*516+k]=f2tf32(w2[(size_t)(n0h+n)*WW+k]);}
    for(int i=tid;i<64*128;i+=NTHR){int n=i>>7,k=i&127;
        sm[O_W1+n*132+k]=f2tf32(w1[(size_t)(n0h+n)*DD+k]);}
    for(int i=tid;i<16*512;i+=NTHR){int n=i>>9,k=i&511;
        sm[O_W3+n*516+k]=f2tf32(w3[(size_t)(n0k+n)*WW+k]);}
    for(int i=tid;i<16*128;i+=NTHR){int n=i>>7,k=i&127;
        sm[O_AM+n*132+k]=f2tf32(Am[(size_t)(n0k+n)*DD+k]);}
    if(tid<64) sm[O_B+tid]=b1[n0h+tid];
    else if(tid<128) sm[O_B+tid]=b2[n0h+tid-64];
    else if(tid<144) sm[O_B+tid-128+128]=b3[n0k+tid-128];
    {   int i=rank*NTHR+tid;   // 4096 elems, 8 ranks x 512 threads
        int r=i>>7,c=i&127; float v=yi[(size_t)(m0+r)*DD+c];
        __stcg(g_y+(size_t)(m0+r)*DD+c,v);
        out[(size_t)(m0+r)*TT*DD+c]=v;}
    cbar();

    const float* b1s=sm+O_B; const float* b2s=sm+O_B+64; const float* b3s=sm+O_B+128;

    for(int t=0;t<TT-1;t++){
        const float h=ts[t+1]-ts[t];
        for(int s=0;s<6;s++){
            float ha[5];
#pragma unroll
            for(int j=0;j<5;j++) ha[j]=h*c_AT[s][j];

            // ================= G1: H1 = tanh(Z @ w1s^T + b1) =================
            {
                float acc[2][4]={{0,0,0,0},{0,0,0,0}};
#pragma unroll
                for(int ck=0;ck<2;ck++){
                    buildZ(buf0,m0,ck*64,s,ha,tid);
                    __syncthreads();
                    mma_n16(buf0,68,sm+O_W1+ck*64,132,acc,wm,wn,ks2,lane);
                    __syncthreads();}
                if(ks2==1){ // partials -> buf1
                    int r0=wm+gid, c=wn+2*tig;
                    *(float2*)(buf1+r0*68+c)    =make_float2(acc[0][0],acc[0][1]);
                    *(float2*)(buf1+(r0+8)*68+c)=make_float2(acc[0][2],acc[0][3]);
                    *(float2*)(buf1+r0*68+c+8)  =make_float2(acc[1][0],acc[1][1]);
                    *(float2*)(buf1+(r0+8)*68+c+8)=make_float2(acc[1][2],acc[1][3]);}
                __syncthreads();
                if(ks2==0){
                    int r0=wm+gid, c=wn+2*tig;
#pragma unroll
                    for(int j=0;j<2;j++){
                        float2 p0=*(float2*)(buf1+r0*68+c+8*j);
                        float2 p1=*(float2*)(buf1+(r0+8)*68+c+8*j);
                        int cg=n0h+c+8*j;
                        float bb0=b1s[c+8*j], bb1=b1s[c+8*j+1];
                        float2 v0=make_float2(f2tf32(ftanh(acc[j][0]+p0.x+bb0)),
                                              f2tf32(ftanh(acc[j][1]+p0.y+bb1)));
                        float2 v1=make_float2(f2tf32(ftanh(acc[j][2]+p1.x+bb0)),
                                              f2tf32(ftanh(acc[j][3]+p1.y+bb1)));
                        __stcg((float2*)(g_h1+(size_t)(m0+r0)*WW+cg),v0);
                        __stcg((float2*)(g_h1+(size_t)(m0+r0+8)*WW+cg),v1);}}
            }
            cbar();

            // ================= G2: H2 = tanh(H1 @ w2s^T + b2) =================
            {
                float acc[2][4]={{0,0,0,0},{0,0,0,0}};
                ldA512(b0b,g_h1+(size_t)m0*WW,tid); cpc();
#pragma unroll
                for(int ck=0;ck<8;ck++){
                    if(ck<7){ldA512(ck&1?b0b:b1b,g_h1+(size_t)m0*WW+(ck+1)*64,tid);
                             cpc(); cpw1();}
                    else cpw0();
                    __syncthreads();
                    mma_n16(ck&1?buf1:buf0,68,sm+O_W2+ck*64,516,acc,wm,wn,ks2,lane);
                    __syncthreads();}
                if(ks2==1){ // partials -> buf0 (free: last chunk was buf1)
                    int r0=wm+gid, c=wn+2*tig;
                    *(float2*)(buf0+r0*68+c)    =make_float2(acc[0][0],acc[0][1]);
                    *(float2*)(buf0+(r0+8)*68+c)=make_float2(acc[0][2],acc[0][3]);
                    *(float2*)(buf0+r0*68+c+8)  =make_float2(acc[1][0],acc[1][1]);
                    *(float2*)(buf0+(r0+8)*68+c+8)=make_float2(acc[1][2],acc[1][3]);}
                __syncthreads();
                if(ks2==0){
                    int r0=wm+gid, c=wn+2*tig;
#pragma unroll
                    for(int j=0;j<2;j++){
                        float2 p0=*(float2*)(buf0+r0*68+c+8*j);
                        float2 p1=*(float2*)(buf0+(r0+8)*68+c+8*j);
                        int cg=n0h+c+8*j;
                        float bb0=b2s[c+8*j], bb1=b2s[c+8*j+1];
                        float2 v0=make_float2(f2tf32(ftanh(acc[j][0]+p0.x+bb0)),
                                              f2tf32(ftanh(acc[j][1]+p0.y+bb1)));
                        float2 v1=make_float2(f2tf32(ftanh(acc[j][2]+p1.x+bb0)),
                                              f2tf32(ftanh(acc[j][3]+p1.y+bb1)));
                        __stcg((float2*)(g_h2+(size_t)(m0+r0)*WW+cg),v0);
                        __stcg((float2*)(g_h2+(size_t)(m0+r0+8)*WW+cg),v1);}}
            }
            cbar();

            // ======== G3: k_s = H2 @ w3s^T + b3 + Z @ Ams^T  (M32 x N16) ========
            {
                float acc[4]={0,0,0,0};
                ldA512(b0b,g_h2+(size_t)m0*WW,tid); cpc();
#pragma unroll
                for(int ck=0;ck<8;ck++){
                    if(ck<7){ldA512(ck&1?b0b:b1b,g_h2+(size_t)m0*WW+(ck+1)*64,tid);
                             cpc(); cpw1();}
                    else cpw0();
                    __syncthreads();
                    mma_n8(ck&1?buf1:buf0,68,sm+O_W3+ck*64,516,acc,wm,wn8,ks4,lane);
                    __syncthreads();}
#pragma unroll
                for(int cz=0;cz<2;cz++){   // Z @ A^T via buf0 (free after ck7 sync)
                    buildZ(buf0,m0,cz*64,s,ha,tid);
                    __syncthreads();
                    mma_n8(buf0,68,sm+O_AM+cz*64,132,acc,wm,wn8,ks4,lane);
                    __syncthreads();}
                if(ks4>0){ // partials -> buf1, slice (ks4-1): 32x16 stride 16
                    float* pr=buf1+(ks4-1)*512;
                    int r0=wm+gid, c=wn8+2*tig;
                    *(float2*)(pr+r0*16+c)    =make_float2(acc[0],acc[1]);
                    *(float2*)(pr+(r0+8)*16+c)=make_float2(acc[2],acc[3]);}
                __syncthreads();
                if(ks4==0){
                    int r0=wm+gid, c=wn8+2*tig;
#pragma unroll
                    for(int p=0;p<3;p++){
                        float* pr=buf1+p*512;
                        float2 q0=*(float2*)(pr+r0*16+c);
                        float2 q1=*(float2*)(pr+(r0+8)*16+c);
                        acc[0]+=q0.x; acc[1]+=q0.y; acc[2]+=q1.x; acc[3]+=q1.y;}
                    float bb0=b3s[c], bb1=b3s[c+1];
                    int cg=n0k+c;
                    float* ksl=g_k[s];
#pragma unroll
                    for(int e=0;e<2;e++){
                        int r=m0+wm+gid+e*8;
                        float kv0=acc[2*e]+bb0, kv1=acc[2*e+1]+bb1;
                        size_t off=(size_t)r*DD+cg;
                        __stcg((float2*)(ksl+off),make_float2(kv0,kv1));
                        if(s==5){
                            float2 yv=__ldcg((const float2*)(g_y+off));
                            float2 k0=__ldcg((const float2*)(g_k[0]+off));
                            float2 k1=__ldcg((const float2*)(g_k[1]+off));
                            float2 k2=__ldcg((const float2*)(g_k[2]+off));
                            float2 k3=__ldcg((const float2*)(g_k[3]+off));
                            float2 k4=__ldcg((const float2*)(g_k[4]+off));
                            float y0=yv.x+h*(c_BT[0]*k0.x+c_BT[1]*k1.x+c_BT[2]*k2.x
                                            +c_BT[3]*k3.x+c_BT[4]*k4.x+c_BT[5]*kv0);
                            float y1=yv.y+h*(c_BT[0]*k0.y+c_BT[1]*k1.y+c_BT[2]*k2.y
                                            +c_BT[3]*k3.y+c_BT[4]*k4.y+c_BT[5]*kv1);
                            __stcg((float2*)(g_y+off),make_float2(y0,y1));
                            *(float2*)(out+(size_t)r*TT*DD+(size_t)(t+1)*DD+cg)
                                =make_float2(y0,y1);}}}
            }
            cbar();
        }
    }
}

extern "C" void kernel_launch(void* const* d_in,const int* in_sizes,int n_in,
                              void* d_out,int out_size){
    (void)in_sizes;(void)n_in;(void)out_size;
    cudaFuncSetAttribute(ode_kernel,cudaFuncAttributeMaxDynamicSharedMemorySize,SMF*4);
    cudaLaunchConfig_t cfg={};
    cfg.gridDim=dim3(128,1,1);
    cfg.blockDim=dim3(NTHR,1,1);
    cfg.dynamicSmemBytes=SMF*4;
    cudaLaunchAttribute at[1];
    at[0].id=cudaLaunchAttributeClusterDimension;
    at[0].val.clusterDim.x=8; at[0].val.clusterDim.y=1; at[0].val.clusterDim.z=1;
    cfg.attrs=at; cfg.numAttrs=1;
    cudaLaunchKernelEx(&cfg,ode_kernel,
        (const float*)d_in[0],(const float*)d_in[1],(const float*)d_in[2],
        (const float*)d_in[3],(const float*)d_in[4],(const float*)d_in[5],
        (const float*)d_in[6],(const float*)d_in[7],(const float*)d_in[8],
        (float*)d_out);
}